// round 17
// baseline (speedup 1.0000x reference)
#include <cuda_runtime.h>
#include <cuda_bf16.h>
#include <stdint.h>
#include <math.h>

#define NN 50000
#define NE 800000
#define NG 64
#define FI 128
#define FH 192
#define FO 128
#define NC 10

// ---------------- device scratch ----------------
__device__ int   g_deg[NN];
__device__ int   g_fill[NN];
__device__ float g_dis[NN];
__device__ int   g_rowptr[NN + 1];
__device__ int   g_bsum[256];
__device__ int   g_boff[256];
__device__ int   g_colidx[NE];
__device__ float g_ew[NE];

__device__ __align__(16) __nv_bfloat16 g_xb[(size_t)NN * FI];
__device__ __align__(16) __nv_bfloat16 g_t1b[(size_t)NN * FH];
__device__ __align__(16) __nv_bfloat16 g_t2b[(size_t)NN * FH];
__device__ __align__(16) __nv_bfloat16 g_h1b[(size_t)NN * FH];
__device__ __align__(16) __nv_bfloat16 g_h2b[(size_t)NN * FH];
__device__ __align__(16) __nv_bfloat16 g_h3b[(size_t)NN * FO];
__device__ __align__(16) __nv_bfloat16 g_wbh[FH * 3 * FH];   // [Fo][K3] hi
__device__ __align__(16) __nv_bfloat16 g_wbl[FH * 3 * FH];   // [Fo][K3] lo
__device__ __align__(16) int8_t g_qa[(size_t)NN * FH];       // int8 prop input (layer input)
__device__ __align__(16) int8_t g_qb[(size_t)NN * FH];       // int8 prop input (T1)
__device__ float g_sa[NN];
__device__ float g_sb[NN];
__device__ float g_pool[NG * FO];
__device__ int   g_cnt[NG];

// NOTE: aarch64 plain `char` is UNSIGNED — must use signed char for sign extension.
__device__ __forceinline__ float s8f(unsigned p, int sh) {
    return (float)(int)(signed char)(p >> sh);
}

// ---------------- graph prep ----------------
__global__ void zero_kernel() {
    int i = blockIdx.x * blockDim.x + threadIdx.x;
    if (i < NN) { g_deg[i] = 0; g_fill[i] = 0; }
    if (i < NG * FO) g_pool[i] = 0.f;
    if (i < NG) g_cnt[i] = 0;
}
__global__ void hist_kernel(const int* __restrict__ ei) {
    int e = blockIdx.x * blockDim.x + threadIdx.x;
    if (e < NE) atomicAdd(&g_deg[ei[e]], 1);
}
__global__ void dis_kernel() {
    int i = blockIdx.x * blockDim.x + threadIdx.x;
    if (i < NN) {
        int d = g_deg[i];
        g_dis[i] = (d > 0) ? rsqrtf((float)d) : 0.f;
    }
}
// x: fp32 -> bf16 (GEMM A) + int8/scale (prop input). warp per row, F=128.
__global__ void conv_x_kernel(const float* __restrict__ x) {
    int gw = (int)((blockIdx.x * (size_t)blockDim.x + threadIdx.x) >> 5);
    int lane = threadIdx.x & 31;
    if (gw >= NN) return;
    float4 v = __ldg(reinterpret_cast<const float4*>(x + (size_t)gw * FI) + lane);
    __nv_bfloat162 b0 = __float22bfloat162_rn(make_float2(v.x, v.y));
    __nv_bfloat162 b1 = __float22bfloat162_rn(make_float2(v.z, v.w));
    uint2 pw;
    pw.x = *reinterpret_cast<unsigned*>(&b0);
    pw.y = *reinterpret_cast<unsigned*>(&b1);
    reinterpret_cast<uint2*>(g_xb + (size_t)gw * FI)[lane] = pw;
    float m = fmaxf(fmaxf(fabsf(v.x), fabsf(v.y)), fmaxf(fabsf(v.z), fabsf(v.w)));
#pragma unroll
    for (int o = 16; o; o >>= 1) m = fmaxf(m, __shfl_xor_sync(0xffffffff, m, o));
    float inv = (m > 0.f) ? 127.f / m : 0.f;
    int q0 = __float2int_rn(v.x * inv), q1 = __float2int_rn(v.y * inv);
    int q2 = __float2int_rn(v.z * inv), q3 = __float2int_rn(v.w * inv);
    unsigned pk = (q0 & 0xff) | ((q1 & 0xff) << 8) | ((q2 & 0xff) << 16) | ((q3 & 0xff) << 24);
    reinterpret_cast<unsigned*>(g_qa + (size_t)gw * FI)[lane] = pk;
    if (lane == 0) g_sa[gw] = m * (1.f / 127.f);
}
// bf16 h (F=192) -> int8/scale. warp per row.
__global__ void quant_h(const __nv_bfloat16* __restrict__ h) {
    int gw = (int)((blockIdx.x * (size_t)blockDim.x + threadIdx.x) >> 5);
    int lane = threadIdx.x & 31;
    if (gw >= NN) return;
    const __nv_bfloat16* hr = h + (size_t)gw * FH;
    uint2 p = reinterpret_cast<const uint2*>(hr)[lane];
    unsigned q = reinterpret_cast<const unsigned*>(hr + 128)[lane];
    __nv_bfloat162 v0 = *reinterpret_cast<__nv_bfloat162*>(&p.x);
    __nv_bfloat162 v1 = *reinterpret_cast<__nv_bfloat162*>(&p.y);
    __nv_bfloat162 v2 = *reinterpret_cast<__nv_bfloat162*>(&q);
    float2 f0 = __bfloat1622float2(v0), f1 = __bfloat1622float2(v1), f2 = __bfloat1622float2(v2);
    float m = fmaxf(fmaxf(fmaxf(fabsf(f0.x), fabsf(f0.y)), fmaxf(fabsf(f1.x), fabsf(f1.y))),
                    fmaxf(fabsf(f2.x), fabsf(f2.y)));
#pragma unroll
    for (int o = 16; o; o >>= 1) m = fmaxf(m, __shfl_xor_sync(0xffffffff, m, o));
    float inv = (m > 0.f) ? 127.f / m : 0.f;
    int q0 = __float2int_rn(f0.x * inv), q1 = __float2int_rn(f0.y * inv);
    int q2 = __float2int_rn(f1.x * inv), q3 = __float2int_rn(f1.y * inv);
    int q4 = __float2int_rn(f2.x * inv), q5 = __float2int_rn(f2.y * inv);
    unsigned pk = (q0 & 0xff) | ((q1 & 0xff) << 8) | ((q2 & 0xff) << 16) | ((q3 & 0xff) << 24);
    int8_t* qr = g_qa + (size_t)gw * FH;
    reinterpret_cast<unsigned*>(qr)[lane] = pk;
    reinterpret_cast<unsigned short*>(qr + 128)[lane] =
        (unsigned short)((q4 & 0xff) | ((q5 & 0xff) << 8));
    if (lane == 0) g_sa[gw] = m * (1.f / 127.f);
}
__global__ void scan1_kernel() {
    __shared__ int ws[8];
    int t = threadIdx.x, b = blockIdx.x;
    int lane = t & 31, w = t >> 5;
    int i = b * 256 + t;
    int v = (i < NN) ? g_deg[i] : 0;
    int incl = v;
#pragma unroll
    for (int d = 1; d < 32; d <<= 1) {
        int n = __shfl_up_sync(0xffffffff, incl, d);
        if (lane >= d) incl += n;
    }
    if (lane == 31) ws[w] = incl;
    __syncthreads();
    if (w == 0 && lane < 8) {
        int s = ws[lane];
#pragma unroll
        for (int d = 1; d < 8; d <<= 1) {
            int n = __shfl_up_sync(0xff, s, d);
            if (lane >= d) s += n;
        }
        ws[lane] = s;
    }
    __syncthreads();
    int off = (w > 0) ? ws[w - 1] : 0;
    incl += off;
    if (i < NN) g_rowptr[i + 1] = incl;
    if (t == 255) g_bsum[b] = incl;
}
__global__ void scan2_kernel(int nblk) {
    __shared__ int ws[8];
    int t = threadIdx.x;
    int lane = t & 31, w = t >> 5;
    int v = (t < nblk) ? g_bsum[t] : 0;
    int incl = v;
#pragma unroll
    for (int d = 1; d < 32; d <<= 1) {
        int n = __shfl_up_sync(0xffffffff, incl, d);
        if (lane >= d) incl += n;
    }
    if (lane == 31) ws[w] = incl;
    __syncthreads();
    if (w == 0 && lane < 8) {
        int s = ws[lane];
#pragma unroll
        for (int d = 1; d < 8; d <<= 1) {
            int n = __shfl_up_sync(0xff, s, d);
            if (lane >= d) s += n;
        }
        ws[lane] = s;
    }
    __syncthreads();
    int off = (w > 0) ? ws[w - 1] : 0;
    g_boff[t] = incl + off - v;
    if (t == 0) g_rowptr[0] = 0;
}
__global__ void scan3_kernel() {
    int i = blockIdx.x * blockDim.x + threadIdx.x;
    if (i < NN) g_rowptr[i + 1] += g_boff[i >> 8];
}
__global__ void fill_kernel(const int* __restrict__ ei) {
    int e = blockIdx.x * blockDim.x + threadIdx.x;
    if (e >= NE) return;
    int r = ei[e];
    int c = ei[NE + e];
    int p = g_rowptr[r] + atomicAdd(&g_fill[r], 1);
    g_colidx[p] = c;
    g_ew[p] = -g_dis[r] * g_dis[c];
}

// ---------------- SpMM: int8 gather + per-row scale, fp32 accum, bf16 out (+opt int8 out) ----------------
template <int F, bool WQ>
__global__ void spmm_q(const int8_t* __restrict__ qin, const float* __restrict__ scl,
                       __nv_bfloat16* __restrict__ bout,
                       int8_t* __restrict__ qout, float* __restrict__ sout) {
    int gw = (int)((blockIdx.x * (size_t)blockDim.x + threadIdx.x) >> 5);
    int lane = threadIdx.x & 31;
    if (gw >= NN) return;
    int s = g_rowptr[gw];
    int e = g_rowptr[gw + 1];
    float a0 = 0.f, a1 = 0.f, a2 = 0.f, a3 = 0.f, a4 = 0.f, a5 = 0.f;
    int i = s;
#define CONSQ(QQ, HH, WE) { \
        a0 = fmaf(WE, s8f(QQ, 0),  a0); a1 = fmaf(WE, s8f(QQ, 8),  a1); \
        a2 = fmaf(WE, s8f(QQ, 16), a2); a3 = fmaf(WE, s8f(QQ, 24), a3); \
        if (F == 192) { a4 = fmaf(WE, s8f(HH, 0), a4); a5 = fmaf(WE, s8f(HH, 8), a5); } }
    for (; i + 8 <= e; i += 8) {
        int cc[8]; float we[8]; unsigned qq[8]; unsigned hh[8];
#pragma unroll
        for (int u = 0; u < 8; u++) {
            cc[u] = __ldg(&g_colidx[i + u]);
            we[u] = __ldg(&g_ew[i + u]);
        }
#pragma unroll
        for (int u = 0; u < 8; u++) we[u] *= __ldg(&scl[cc[u]]);
#pragma unroll
        for (int u = 0; u < 8; u++) {
            qq[u] = __ldg(reinterpret_cast<const unsigned*>(qin + (size_t)cc[u] * F) + lane);
            if (F == 192)
                hh[u] = __ldg(reinterpret_cast<const unsigned short*>(qin + (size_t)cc[u] * F + 128) + lane);
            else hh[u] = 0;
        }
#pragma unroll
        for (int u = 0; u < 8; u++) CONSQ(qq[u], hh[u], we[u]);
    }
    for (; i < e; i++) {
        int c = __ldg(&g_colidx[i]);
        float we = __ldg(&g_ew[i]) * __ldg(&scl[c]);
        unsigned q = __ldg(reinterpret_cast<const unsigned*>(qin + (size_t)c * F) + lane);
        unsigned h = 0;
        if (F == 192)
            h = __ldg(reinterpret_cast<const unsigned short*>(qin + (size_t)c * F + 128) + lane);
        CONSQ(q, h, we);
    }
#undef CONSQ
    // bf16 output
    __nv_bfloat16* b = bout + (size_t)gw * F;
    __nv_bfloat162 b0 = __float22bfloat162_rn(make_float2(a0, a1));
    __nv_bfloat162 b1 = __float22bfloat162_rn(make_float2(a2, a3));
    uint2 pw;
    pw.x = *reinterpret_cast<unsigned*>(&b0);
    pw.y = *reinterpret_cast<unsigned*>(&b1);
    reinterpret_cast<uint2*>(b)[lane] = pw;
    if (F == 192) {
        __nv_bfloat162 b2 = __float22bfloat162_rn(make_float2(a4, a5));
        reinterpret_cast<unsigned*>(b + 128)[lane] = *reinterpret_cast<unsigned*>(&b2);
    }
    // optional int8 output (prop input for the next SpMM)
    if (WQ) {
        float m = fmaxf(fmaxf(fabsf(a0), fabsf(a1)), fmaxf(fabsf(a2), fabsf(a3)));
        if (F == 192) m = fmaxf(m, fmaxf(fabsf(a4), fabsf(a5)));
#pragma unroll
        for (int o = 16; o; o >>= 1) m = fmaxf(m, __shfl_xor_sync(0xffffffff, m, o));
        float inv = (m > 0.f) ? 127.f / m : 0.f;
        int q0 = __float2int_rn(a0 * inv), q1 = __float2int_rn(a1 * inv);
        int q2 = __float2int_rn(a2 * inv), q3 = __float2int_rn(a3 * inv);
        unsigned pk = (q0 & 0xff) | ((q1 & 0xff) << 8) | ((q2 & 0xff) << 16) | ((q3 & 0xff) << 24);
        int8_t* qr = qout + (size_t)gw * F;
        reinterpret_cast<unsigned*>(qr)[lane] = pk;
        if (F == 192) {
            int q4 = __float2int_rn(a4 * inv), q5 = __float2int_rn(a5 * inv);
            reinterpret_cast<unsigned short*>(qr + 128)[lane] =
                (unsigned short)((q4 & 0xff) | ((q5 & 0xff) << 8));
        }
        if (lane == 0) sout[gw] = m * (1.f / 127.f);
    }
}

// ---------------- weight fold + transpose: [Fo][K3], bf16 hi/lo split ----------------
__global__ void prep_wT(const float* __restrict__ W, int Fin, int Fo) {
    int i = blockIdx.x * blockDim.x + threadIdx.x;
    int K3 = 3 * Fin;
    if (i >= Fo * K3) return;
    int o = i / K3, j = i - o * K3;
    int term = j / Fin, ii = j - term * Fin;
    float v;
    if (term == 0)      v = W[(size_t)ii * Fo + o] - W[(size_t)(2 * Fin + ii) * Fo + o];
    else if (term == 1) v = W[(size_t)(Fin + ii) * Fo + o];
    else                v = 2.f * W[(size_t)(2 * Fin + ii) * Fo + o];
    __nv_bfloat16 hi = __float2bfloat16(v);
    g_wbh[i] = hi;
    g_wbl[i] = __float2bfloat16(v - __bfloat162float(hi));
}

// ---------------- bf16 m16n8k16 GEMM with ldmatrix fragment loads ----------------
#define ASTR 20

#define MMA_BF16(c, A_, B_) \
    asm volatile("mma.sync.aligned.m16n8k16.row.col.f32.bf16.bf16.f32 " \
                 "{%0,%1,%2,%3},{%4,%5,%6,%7},{%8,%9},{%0,%1,%2,%3};" \
                 : "+f"((c)[0]), "+f"((c)[1]), "+f"((c)[2]), "+f"((c)[3]) \
                 : "r"((A_)[0]), "r"((A_)[1]), "r"((A_)[2]), "r"((A_)[3]), \
                   "r"((B_)[0]), "r"((B_)[1]))

#define LDSM4(r0, r1, r2, r3, addr) \
    asm volatile("ldmatrix.sync.aligned.m8n8.x4.shared.b16 {%0,%1,%2,%3}, [%4];" \
                 : "=r"(r0), "=r"(r1), "=r"(r2), "=r"(r3) : "r"(addr))

__global__ __launch_bounds__(128) void gemm_cheb(
    const __nv_bfloat16* __restrict__ h, const __nv_bfloat16* __restrict__ t1p,
    const __nv_bfloat16* __restrict__ t2p, const float* __restrict__ bias,
    __nv_bfloat16* __restrict__ outb, int Fin, int Fo)
{
    __shared__ __align__(16) unsigned As[128 * ASTR];
    __shared__ __align__(16) unsigned BsH[64 * ASTR];
    __shared__ __align__(16) unsigned BsL[64 * ASTR];

    int tid = threadIdx.x;
    int lane = tid & 31;
    int warp = tid >> 5;
    int wm = warp >> 1;
    int wn = warp & 1;
    int tile_m = blockIdx.x * 128;
    int tile_n = blockIdx.y * 64;
    int K3 = 3 * Fin;
    const __nv_bfloat16* bufs[3] = { h, t1p, t2p };

    uint32_t sA  = (uint32_t)__cvta_generic_to_shared(As);
    uint32_t sBH = (uint32_t)__cvta_generic_to_shared(BsH);
    uint32_t sBL = (uint32_t)__cvta_generic_to_shared(BsL);

    int g  = lane >> 3;
    int lr = lane & 7;
    int a_row_lane = (g & 1) * 8 + lr;
    int a_seg_lane = g >> 1;
    int b_col_lane = (g >> 1) * 8 + lr;
    int b_seg_lane = g & 1;

    float acc[4][4][4];
#pragma unroll
    for (int a = 0; a < 4; a++)
#pragma unroll
        for (int b = 0; b < 4; b++)
#pragma unroll
            for (int c = 0; c < 4; c++) acc[a][b][c] = 0.f;

    for (int k0 = 0; k0 < K3; k0 += 32) {
        const __nv_bfloat16* A = bufs[k0 / Fin];
        int kl = k0 % Fin;
#pragma unroll
        for (int j = 0; j < 4; j++) {
            int idx = j * 128 + tid;
            int m = idx >> 2, kq = idx & 3;
            int gm = tile_m + m;
            uint4 v = make_uint4(0u, 0u, 0u, 0u);
            if (gm < NN)
                v = *reinterpret_cast<const uint4*>(A + (size_t)gm * Fin + kl + kq * 8);
            *reinterpret_cast<uint4*>(&As[m * ASTR + kq * 4]) = v;
        }
#pragma unroll
        for (int j = 0; j < 2; j++) {
            int idx = j * 128 + tid;
            int n = idx >> 2, kq = idx & 3;
            size_t gsrc = (size_t)(tile_n + n) * K3 + k0 + kq * 8;
            *reinterpret_cast<uint4*>(&BsH[n * ASTR + kq * 4]) =
                *reinterpret_cast<const uint4*>(g_wbh + gsrc);
            *reinterpret_cast<uint4*>(&BsL[n * ASTR + kq * 4]) =
                *reinterpret_cast<const uint4*>(g_wbl + gsrc);
        }
        __syncthreads();

#pragma unroll
        for (int ks = 0; ks < 2; ks++) {
            unsigned a[4][4], bh[4][2], bl[4][2];
#pragma unroll
            for (int mt = 0; mt < 4; mt++) {
                uint32_t ad = sA + (uint32_t)(((wm * 64 + mt * 16 + a_row_lane) * ASTR
                              + (ks * 2 + a_seg_lane) * 4) * 4);
                LDSM4(a[mt][0], a[mt][1], a[mt][2], a[mt][3], ad);
            }
#pragma unroll
            for (int p = 0; p < 2; p++) {
                uint32_t off = (uint32_t)(((wn * 32 + p * 16 + b_col_lane) * ASTR
                              + (ks * 2 + b_seg_lane) * 4) * 4);
                LDSM4(bh[2 * p][0], bh[2 * p][1], bh[2 * p + 1][0], bh[2 * p + 1][1], sBH + off);
                LDSM4(bl[2 * p][0], bl[2 * p][1], bl[2 * p + 1][0], bl[2 * p + 1][1], sBL + off);
            }
#pragma unroll
            for (int mt = 0; mt < 4; mt++)
#pragma unroll
                for (int nt = 0; nt < 4; nt++) {
                    MMA_BF16(acc[mt][nt], a[mt], bh[nt]);
                    MMA_BF16(acc[mt][nt], a[mt], bl[nt]);
                }
        }
        __syncthreads();
    }

#pragma unroll
    for (int mt = 0; mt < 4; mt++) {
        int r0 = tile_m + wm * 64 + mt * 16 + (lane >> 2);
#pragma unroll
        for (int nt = 0; nt < 4; nt++) {
            int c0 = tile_n + wn * 32 + nt * 8 + 2 * (lane & 3);
            float2 bb = *reinterpret_cast<const float2*>(bias + c0);
            if (r0 < NN) {
                __nv_bfloat162 o = __float22bfloat162_rn(
                    make_float2(acc[mt][nt][0] + bb.x, acc[mt][nt][1] + bb.y));
                *reinterpret_cast<__nv_bfloat162*>(outb + (size_t)r0 * Fo + c0) = o;
            }
            if (r0 + 8 < NN) {
                __nv_bfloat162 o = __float22bfloat162_rn(
                    make_float2(acc[mt][nt][2] + bb.x, acc[mt][nt][3] + bb.y));
                *reinterpret_cast<__nv_bfloat162*>(outb + (size_t)(r0 + 8) * Fo + c0) = o;
            }
        }
    }
}

// ---------------- global mean pool (bf16 input) ----------------
__global__ void pool_kernel(const __nv_bfloat16* __restrict__ h, const int* __restrict__ batch) {
    int t = threadIdx.x;
    int base = blockIdx.x * 128;
    int cur = -1;
    float acc = 0.f;
    int cnt = 0;
    for (int n = 0; n < 128; n++) {
        int g = base + n;
        if (g >= NN) break;
        int bg = batch[g];
        if (bg != cur) {
            if (cur >= 0) {
                atomicAdd(&g_pool[cur * FO + t], acc);
                if (t == 0) atomicAdd(&g_cnt[cur], cnt);
            }
            cur = bg; acc = 0.f; cnt = 0;
        }
        acc += __bfloat162float(h[(size_t)g * FO + t]);
        cnt++;
    }
    if (cur >= 0) {
        atomicAdd(&g_pool[cur * FO + t], acc);
        if (t == 0) atomicAdd(&g_cnt[cur], cnt);
    }
}

// ---------------- FC + log_softmax ----------------
__global__ void final_kernel(const float* __restrict__ fcw, const float* __restrict__ fcb,
                             float* __restrict__ out) {
    __shared__ float lg[NG][NC];
    __shared__ float smax[NG], slse[NG];
    int t = threadIdx.x;
    if (t < NG * NC) {
        int g = t / NC, c = t % NC;
        float inv = 1.f / fmaxf((float)g_cnt[g], 1.f);
        float s = fcb[c];
        for (int f = 0; f < FO; f++)
            s = fmaf(g_pool[g * FO + f] * inv, fcw[f * NC + c], s);
        lg[g][c] = s;
    }
    __syncthreads();
    if (t < NG) {
        float m = -1e30f;
        for (int c = 0; c < NC; c++) m = fmaxf(m, lg[t][c]);
        float se = 0.f;
        for (int c = 0; c < NC; c++) se += expf(lg[t][c] - m);
        smax[t] = m;
        slse[t] = logf(se);
    }
    __syncthreads();
    if (t < NG * NC) {
        int g = t / NC, c = t % NC;
        out[t] = lg[g][c] - smax[g] - slse[g];
    }
}

// ---------------- launch ----------------
extern "C" void kernel_launch(void* const* d_in, const int* in_sizes, int n_in,
                              void* d_out, int out_size) {
    const float* x   = (const float*)d_in[0];
    const int*   ei  = (const int*)d_in[1];
    const int*   bat = (const int*)d_in[2];
    const float* W1  = (const float*)d_in[3];
    const float* b1  = (const float*)d_in[4];
    const float* W2  = (const float*)d_in[5];
    const float* b2  = (const float*)d_in[6];
    const float* W3  = (const float*)d_in[7];
    const float* b3  = (const float*)d_in[8];
    const float* fcw = (const float*)d_in[9];
    const float* fcb = (const float*)d_in[10];
    float* out = (float*)d_out;

    __nv_bfloat16 *xb, *t1b, *t2b, *h1b, *h2b, *h3b;
    int8_t *qa, *qb;
    float *sa, *sb;
    cudaGetSymbolAddress((void**)&xb,  g_xb);
    cudaGetSymbolAddress((void**)&t1b, g_t1b);
    cudaGetSymbolAddress((void**)&t2b, g_t2b);
    cudaGetSymbolAddress((void**)&h1b, g_h1b);
    cudaGetSymbolAddress((void**)&h2b, g_h2b);
    cudaGetSymbolAddress((void**)&h3b, g_h3b);
    cudaGetSymbolAddress((void**)&qa, g_qa);
    cudaGetSymbolAddress((void**)&qb, g_qb);
    cudaGetSymbolAddress((void**)&sa, g_sa);
    cudaGetSymbolAddress((void**)&sb, g_sb);

    const int NB = (NN + 255) / 256;
    const int warpBlocks = (NN * 32 + 255) / 256;

    zero_kernel<<<(NN + 255) / 256, 256>>>();
    hist_kernel<<<(NE + 255) / 256, 256>>>(ei);
    dis_kernel<<<(NN + 255) / 256, 256>>>();
    conv_x_kernel<<<warpBlocks, 256>>>(x);
    scan1_kernel<<<NB, 256>>>();
    scan2_kernel<<<1, 256>>>(NB);
    scan3_kernel<<<NB, 256>>>();
    fill_kernel<<<(NE + 255) / 256, 256>>>(ei);

    dim3 gemmGridH((NN + 127) / 128, FH / 64);
    dim3 gemmGridO((NN + 127) / 128, FO / 64);

    // layer 1: Fin=128 -> Fo=192
    spmm_q<FI, true ><<<warpBlocks, 256>>>(qa, sa, t1b, qb, sb);
    spmm_q<FI, false><<<warpBlocks, 256>>>(qb, sb, t2b, nullptr, nullptr);
    prep_wT<<<(FH * 3 * FI + 255) / 256, 256>>>(W1, FI, FH);
    gemm_cheb<<<gemmGridH, 128>>>(xb, t1b, t2b, b1, h1b, FI, FH);

    // layer 2: Fin=192 -> Fo=192
    quant_h<<<warpBlocks, 256>>>(h1b);
    spmm_q<FH, true ><<<warpBlocks, 256>>>(qa, sa, t1b, qb, sb);
    spmm_q<FH, false><<<warpBlocks, 256>>>(qb, sb, t2b, nullptr, nullptr);
    prep_wT<<<(FH * 3 * FH + 255) / 256, 256>>>(W2, FH, FH);
    gemm_cheb<<<gemmGridH, 128>>>(h1b, t1b, t2b, b2, h2b, FH, FH);

    // layer 3: Fin=192 -> Fo=128
    quant_h<<<warpBlocks, 256>>>(h2b);
    spmm_q<FH, true ><<<warpBlocks, 256>>>(qa, sa, t1b, qb, sb);
    spmm_q<FH, false><<<warpBlocks, 256>>>(qb, sb, t2b, nullptr, nullptr);
    prep_wT<<<(FO * 3 * FH + 255) / 256, 256>>>(W3, FH, FO);
    gemm_cheb<<<gemmGridO, 128>>>(h2b, t1b, t2b, b3, h3b, FH, FO);

    pool_kernel<<<(NN + 127) / 128, 128>>>(h3b, bat);
    final_kernel<<<1, 640>>>(fcw, fcb, out);
}